// round 16
// baseline (speedup 1.0000x reference)
#include <cuda_runtime.h>
#include <cuda_fp16.h>
#include <cstdint>

#define NH    7
#define HD    128
#define BB    4
#define TT    2048
#define HID   896
#define MTOT  (BB*TT)   // 8192
#define CPAD  896       // padded compact length (>= max 879, multiple of 64)

// Scratch (allocation-free rule: __device__ globals).  All MMA operands fp16,
// stored k-permuted in 32-groups: chunk lc (8 halves) holds k =
// {2lc,2lc+1, 2lc+8,2lc+9, 2lc+16,2lc+17, 2lc+24,2lc+25}.
__device__ __half g_xt[(size_t)MTOT * HID];
__device__ __half g_wt[(size_t)21 * HD * HID];
__device__ __half g_wot[(size_t)HID * HID];
__device__ __half g_q[(size_t)NH * MTOT * HD];
__device__ __half g_k[(size_t)NH * MTOT * HD];
__device__ __half g_v[(size_t)NH * MTOT * HD];
__device__ __half g_kc[(size_t)NH * BB * CPAD * HD];   // compacted K [slot][d perm]
__device__ __half g_vct[(size_t)NH * BB * HD * CPAD];  // compacted V^T [d][perm(slot)]
__device__ __half g_att[(size_t)MTOT * HID];

__device__ __forceinline__ void mma16(float& d0, float& d1, float& d2, float& d3,
                                      unsigned a0, unsigned a1, unsigned a2, unsigned a3,
                                      unsigned b0, unsigned b1) {
    asm volatile(
        "mma.sync.aligned.m16n8k16.row.col.f32.f16.f16.f32 "
        "{%0,%1,%2,%3}, {%4,%5,%6,%7}, {%8,%9}, {%0,%1,%2,%3};\n"
        : "+f"(d0), "+f"(d1), "+f"(d2), "+f"(d3)
        : "r"(a0), "r"(a1), "r"(a2), "r"(a3), "r"(b0), "r"(b1));
}

// conflict-free 16B-chunk swizzle: XOR low 3 bits with perm(row)
__device__ __forceinline__ int permq(int row) { return ((row & 1) << 2) | ((row >> 1) & 3); }
__device__ __forceinline__ int swq(int lch, int row) {
    return (lch & ~7) | ((lch & 7) ^ permq(row));
}

__device__ __forceinline__ void cp16(void* dst, const void* src) {
    unsigned d = (unsigned)__cvta_generic_to_shared(dst);
    asm volatile("cp.async.cg.shared.global [%0], [%1], 16;" :: "r"(d), "l"(src));
}
__device__ __forceinline__ void cp_commit() { asm volatile("cp.async.commit_group;"); }
template<int N> __device__ __forceinline__ void cp_wait() {
    asm volatile("cp.async.wait_group %0;" :: "n"(N));
}

// ===========================================================================
// Prep kernels: fp16 conversion + 32-wide k-perm
// ===========================================================================
__global__ void prep_perm(const float* __restrict__ src, __half* __restrict__ dst, int total32)
{
    int t = blockIdx.x * 256 + threadIdx.x;
    if (t >= total32) return;
    const float* s = src + (size_t)t * 32;
    float in[32];
    #pragma unroll
    for (int i = 0; i < 8; i++) {
        float4 v = ((const float4*)s)[i];
        in[4*i] = v.x; in[4*i+1] = v.y; in[4*i+2] = v.z; in[4*i+3] = v.w;
    }
    __half2* d = (__half2*)(dst + (size_t)t * 32);
    #pragma unroll
    for (int lc = 0; lc < 4; lc++) {
        d[lc*4 + 0] = __floats2half2_rn(in[2*lc],      in[2*lc + 1]);
        d[lc*4 + 1] = __floats2half2_rn(in[2*lc + 8],  in[2*lc + 9]);
        d[lc*4 + 2] = __floats2half2_rn(in[2*lc + 16], in[2*lc + 17]);
        d[lc*4 + 3] = __floats2half2_rn(in[2*lc + 24], in[2*lc + 25]);
    }
}

// W[h][896][128] -> g_wt[z][n][896] transposed + perm32
__global__ void prep_wt(const float* __restrict__ Wq, const float* __restrict__ Wk,
                        const float* __restrict__ Wv)
{
    __shared__ float tb[32][33];
    int z = blockIdx.z, h = z / 3, sel = z % 3;
    const float* W = (sel == 0 ? Wq : (sel == 1 ? Wk : Wv)) + (size_t)h * HID * HD;
    int k0 = blockIdx.x * 32, n0 = blockIdx.y * 32;
    int tx = threadIdx.x, ty = threadIdx.y;
    #pragma unroll
    for (int i = 0; i < 4; i++)
        tb[ty + 8 * i][tx] = W[(size_t)(k0 + ty + 8 * i) * HD + n0 + tx];
    __syncthreads();
    int al = 16 * ((tx >> 2) & 1) + 8 * ((tx >> 1) & 1) + 2 * (tx >> 3) + (tx & 1);
    #pragma unroll
    for (int i = 0; i < 4; i++) {
        int n = n0 + ty + 8 * i;
        g_wt[((size_t)z * HD + n) * HID + k0 + tx] = __float2half_rn(tb[al][ty + 8 * i]);
    }
}

__device__ __forceinline__ void fano_lines(int h, int& s0, int& s1, int& s2, int& cnt)
{
    int t;
    s0 = h; s1 = (h + 1) % 7; s2 = (h + 3) % 7;
    if (s0 > s1) { t = s0; s0 = s1; s1 = t; }
    if (s1 > s2) { t = s1; s1 = s2; s2 = t; }
    if (s0 > s1) { t = s0; s0 = s1; s1 = t; }
    cnt = 3 * 292 + (s0 < 4) + (s1 < 4) + (s2 < 4);
}

__global__ void __launch_bounds__(256) compact_k()
{
    int h = blockIdx.y >> 2, b = blockIdx.y & 3;
    int tid = threadIdx.x;
    int c = blockIdx.x * 64 + (tid >> 2);
    int seg = tid & 3;
    int s0, s1, s2, cnt;
    fano_lines(h, s0, s1, s2, cnt);
    int q = c / 3, u = c - 3 * q;
    int sl = (u == 0) ? s0 : ((u == 1) ? s1 : s2);
    int o = 7 * q + sl;
    bool valid = c < cnt;
    size_t sb = ((size_t)(h * BB + b) * TT + o) * HD + seg * 32;
    size_t db = ((size_t)(h * BB + b) * CPAD + c) * HD + seg * 32;
    uint4 z4 = make_uint4(0, 0, 0, 0);
    #pragma unroll
    for (int i = 0; i < 4; i++)
        *(uint4*)&g_kc[db + i * 8] = valid ? *(const uint4*)&g_k[sb + i * 8] : z4;
}

// V compaction + transpose: g_vct[d][c0 + pos32(c_local)] = V[slot(c)][d]
__global__ void compact_vT()   // grid (CPAD/32, HD/32, 28), block (32, 8)
{
    __shared__ __half tb[32][33];
    int z = blockIdx.z, h = z >> 2, b = z & 3;
    int s0, s1, s2, cnt;
    fano_lines(h, s0, s1, s2, cnt);
    int c0 = blockIdx.x * 32, d0 = blockIdx.y * 32;
    int tx = threadIdx.x, ty = threadIdx.y;
    const __half* Vsrc = g_v + (size_t)(h * BB + b) * TT * HD;
    size_t dstb = (size_t)(h * BB + b) * HD * CPAD;
    int al = 16 * ((tx >> 2) & 1) + 8 * ((tx >> 1) & 1) + 2 * (tx >> 3) + (tx & 1);
    #pragma unroll
    for (int i = 0; i < 4; i++) {
        int c = c0 + ty + 8 * i;
        int q = c / 3, u = c - 3 * q;
        int sl = (u == 0) ? s0 : ((u == 1) ? s1 : s2);
        int og = 7 * q + sl;
        __half val = (c < cnt) ? Vsrc[(size_t)og * HD + d0 + tx] : __float2half(0.f);
        tb[ty + 8 * i][al] = val;
    }
    __syncthreads();
    int destc = c0 + ((tx >> 1) & 3) * 8 + ((tx >> 4) & 1) * 4 + ((tx >> 3) & 1) * 2 + (tx & 1);
    #pragma unroll
    for (int i = 0; i < 4; i++) {
        int d = d0 + ty + 8 * i;
        g_vct[dstb + (size_t)d * CPAD + destc] = tb[tx][ty + 8 * i];
    }
}

// ===========================================================================
// fp16 GEMM (unchanged from R14): 128x128 CTA, 4 warps 64x64, BK=64, 3-stage
// ===========================================================================
#define GSMEM 98304

__device__ __forceinline__ void gemm_issue(const __half* __restrict__ A,
                                           const __half* __restrict__ B,
                                           char* As, char* Bs,
                                           int kb, int m0, int n0, int tid)
{
    #pragma unroll
    for (int j = 0; j < 8; j++) {
        int idx = tid + 128 * j;
        int row = idx >> 3, ch = idx & 7;
        cp16(As + row * 128 + swq(ch, row) * 16, A + (size_t)(m0 + row) * HID + kb * 64 + ch * 8);
    }
    #pragma unroll
    for (int j = 0; j < 8; j++) {
        int idx = tid + 128 * j;
        int row = idx >> 3, ch = idx & 7;
        cp16(Bs + row * 128 + swq(ch, row) * 16, B + (size_t)(n0 + row) * HID + kb * 64 + ch * 8);
    }
    cp_commit();
}

template<bool PERM>
__device__ __forceinline__ void gemm_main(const __half* __restrict__ A,
                                          const __half* __restrict__ B,
                                          void* Cv, int ldc, int m0, int n0)
{
    extern __shared__ char sg[];
    int tid = threadIdx.x, lane = tid & 31, wid = tid >> 5;
    int wm = (wid >> 1) * 64, wn = (wid & 1) * 64;
    int r = lane >> 2, lc = lane & 3;

    float acc[4][8][4];
    #pragma unroll
    for (int f = 0; f < 4; f++)
        #pragma unroll
        for (int nf = 0; nf < 8; nf++)
            #pragma unroll
            for (int e = 0; e < 4; e++) acc[f][nf][e] = 0.f;

    gemm_issue(A, B, sg,         sg + 16384,         0, m0, n0, tid);
    gemm_issue(A, B, sg + 32768, sg + 32768 + 16384, 1, m0, n0, tid);

    #pragma unroll 1
    for (int kb = 0; kb < 14; kb++) {
        int st = kb % 3;
        char* As = sg + st * 32768;
        char* Bs = As + 16384;
        cp_wait<1>();
        __syncthreads();
        #pragma unroll
        for (int G = 0; G < 2; G++) {
            int off = swq(G * 4 + lc, r) * 16;
            uint4 alo[4], ahi[4];
            #pragma unroll
            for (int mf = 0; mf < 4; mf++) {
                int row = wm + mf * 16 + r;
                alo[mf] = *(const uint4*)(As + row * 128 + off);
                ahi[mf] = *(const uint4*)(As + (row + 8) * 128 + off);
            }
            uint4 bb[8];
            #pragma unroll
            for (int nf = 0; nf < 8; nf++)
                bb[nf] = *(const uint4*)(Bs + (wn + nf * 8 + r) * 128 + off);
            #pragma unroll
            for (int mf = 0; mf < 4; mf++)
                #pragma unroll
                for (int nf = 0; nf < 8; nf++) {
                    mma16(acc[mf][nf][0], acc[mf][nf][1], acc[mf][nf][2], acc[mf][nf][3],
                          alo[mf].x, ahi[mf].x, alo[mf].y, ahi[mf].y, bb[nf].x, bb[nf].y);
                    mma16(acc[mf][nf][0], acc[mf][nf][1], acc[mf][nf][2], acc[mf][nf][3],
                          alo[mf].z, ahi[mf].z, alo[mf].w, ahi[mf].w, bb[nf].z, bb[nf].w);
                }
        }
        if (kb + 2 < 14) {
            int ns = (kb + 2) % 3;
            gemm_issue(A, B, sg + ns * 32768, sg + ns * 32768 + 16384, kb + 2, m0, n0, tid);
        } else {
            cp_commit();
        }
    }

    #pragma unroll
    for (int mf = 0; mf < 4; mf++) {
        int row = m0 + wm + mf * 16 + r;
        #pragma unroll
        for (int nf = 0; nf < 8; nf++) {
            if (PERM) {
                __half* C = (__half*)Cv;
                int cb = n0 + wn + (nf >> 2) * 32 + lc * 8 + ((nf >> 1) & 1) * 4 + (nf & 1) * 2;
                *(__half2*)&C[(size_t)row * ldc + cb] =
                    __floats2half2_rn(acc[mf][nf][0], acc[mf][nf][1]);
                *(__half2*)&C[(size_t)(row + 8) * ldc + cb] =
                    __floats2half2_rn(acc[mf][nf][2], acc[mf][nf][3]);
            } else {
                float* C = (float*)Cv;
                int cb = n0 + wn + nf * 8 + 2 * lc;
                *(float2*)&C[(size_t)row * ldc + cb] =
                    make_float2(acc[mf][nf][0], acc[mf][nf][1]);
                *(float2*)&C[(size_t)(row + 8) * ldc + cb] =
                    make_float2(acc[mf][nf][2], acc[mf][nf][3]);
            }
        }
    }
}

__global__ void __launch_bounds__(128, 2) proj_tc()
{
    int z = blockIdx.y;
    __half* out = ((z % 3) == 0 ? g_q : ((z % 3) == 1 ? g_k : g_v)) + (size_t)(z / 3) * MTOT * HD;
    gemm_main<true>(g_xt, g_wt + (size_t)z * HD * HID, out, HD, blockIdx.x * 128, 0);
}

__global__ void __launch_bounds__(128, 2) outproj_tc(float* __restrict__ out)
{
    gemm_main<false>(g_att, g_wot, out, HID, blockIdx.x * 128, blockIdx.y * 128);
}

// ===========================================================================
// fp16 flash attention, BM=128, 256 threads (8 warps x m16).  Q staged once
// in smem (frees 32 regs/thread); K/V staging + syncs halved per unit work.
// Smem: Qs 32KB | Kb 16KB | Vb 16KB | Ps 16KB = 80KB.
// ===========================================================================
#define QS_OFF 0
#define KB_OFF 32768
#define VB_OFF 49152
#define PS_OFF 65536
#define ATTN_SM 81920

#define SCLC (0.08838834764831845f * 1.4426950408889634f)

template<int NFB>
__device__ __forceinline__ void band_tile(
    int bstart, int causal,
    const __half* __restrict__ Kf, const __half* __restrict__ Vf,
    char* QsC, char* KbC, char* VbC, char* PsC,
    float (&o)[16][4],
    float& m_lo, float& m_hi, float& l_lo, float& l_hi,
    int tid, int r, int lc, int rloc, int rowq)
{
    // stage K rows [bstart, bstart+8*NFB)
    #pragma unroll
    for (int j = 0; j < NFB / 2; j++) {
        int idx = tid + 256 * j;
        int nn = idx >> 4, ch = idx & 15;
        int og = bstart + nn;
        uint4 v = (og >= 0 && og < TT)
            ? *(const uint4*)(Kf + (size_t)og * HD + ch * 8)
            : make_uint4(0, 0, 0, 0);
        *(uint4*)(KbC + nn * 256 + swq(ch, nn) * 16) = v;
    }
    __syncthreads();

    float s[NFB][4];
    #pragma unroll
    for (int nf = 0; nf < NFB; nf++)
        #pragma unroll
        for (int e = 0; e < 4; e++) s[nf][e] = 0.f;
    #pragma unroll
    for (int G = 0; G < 4; G++) {
        int off = swq(G * 4 + lc, r) * 16;      // permq(rloc)==permq(r)
        uint4 qlo = *(const uint4*)(QsC + rloc * 256 + off);
        uint4 qhi = *(const uint4*)(QsC + (rloc + 8) * 256 + off);
        #pragma unroll
        for (int nf = 0; nf < NFB; nf++) {
            uint4 bb = *(const uint4*)(KbC + (nf * 8 + r) * 256 + off);
            mma16(s[nf][0], s[nf][1], s[nf][2], s[nf][3],
                  qlo.x, qhi.x, qlo.y, qhi.y, bb.x, bb.y);
            mma16(s[nf][0], s[nf][1], s[nf][2], s[nf][3],
                  qlo.z, qhi.z, qlo.w, qhi.w, bb.z, bb.w);
        }
    }

    float mx_lo = -1e30f, mx_hi = -1e30f;
    int gi_lo = rowq, gi_hi = rowq + 8;
    #pragma unroll
    for (int nf = 0; nf < NFB; nf++) {
        #pragma unroll
        for (int t = 0; t < 2; t++) {
            int og = bstart + nf * 8 + 2 * lc + t;
            bool ok_lo, ok_hi;
            if (causal) {
                ok_lo = (og >= gi_lo - 16) && (og <= gi_lo) && (og >= 0);
                ok_hi = (og >= gi_hi - 16) && (og <= gi_hi) && (og >= 0);
            } else {
                bool inr = (og >= 0) && (og < TT);
                ok_lo = inr && (og >= gi_lo - 16) && (og <= gi_lo + 16);
                ok_hi = inr && (og >= gi_hi - 16) && (og <= gi_hi + 16);
            }
            float vlo = ok_lo ? s[nf][t] * SCLC : -1e30f;
            float vhi = ok_hi ? s[nf][2 + t] * SCLC : -1e30f;
            s[nf][t] = vlo; s[nf][2 + t] = vhi;
            mx_lo = fmaxf(mx_lo, vlo); mx_hi = fmaxf(mx_hi, vhi);
        }
    }
    mx_lo = fmaxf(mx_lo, __shfl_xor_sync(0xffffffffu, mx_lo, 1));
    mx_lo = fmaxf(mx_lo, __shfl_xor_sync(0xffffffffu, mx_lo, 2));
    mx_hi = fmaxf(mx_hi, __shfl_xor_sync(0xffffffffu, mx_hi, 1));
    mx_hi = fmaxf(mx_hi, __shfl_xor_sync(0xffffffffu, mx_hi, 2));

    float mn_lo = fmaxf(fmaxf(m_lo, mx_lo), -1e28f);
    float mn_hi = fmaxf(fmaxf(m_hi, mx_hi), -1e28f);
    float cor_lo = exp2f(m_lo - mn_lo), cor_hi = exp2f(m_hi - mn_hi);
    m_lo = mn_lo; m_hi = mn_hi;

    float sum_lo = 0.f, sum_hi = 0.f;
    #pragma unroll
    for (int nf = 0; nf < NFB; nf++) {
        float p0 = exp2f(s[nf][0] - mn_lo);
        float p1 = exp2f(s[nf][1] - mn_lo);
        float p2 = exp2f(s[nf][2] - mn_hi);
        float p3 = exp2f(s[nf][3] - mn_hi);
        sum_lo += p0 + p1; sum_hi += p2 + p3;
        int boff = swq((nf >> 2) * 4 + lc, rloc) * 16 + (((nf >> 1) & 1) * 4 + (nf & 1) * 2) * 2;
        *(__half2*)(PsC + rloc * 128 + boff)       = __floats2half2_rn(p0, p1);
        *(__half2*)(PsC + (rloc + 8) * 128 + boff) = __floats2half2_rn(p2, p3);
    }
    sum_lo += __shfl_xor_sync(0xffffffffu, sum_lo, 1);
    sum_lo += __shfl_xor_sync(0xffffffffu, sum_lo, 2);
    sum_hi += __shfl_xor_sync(0xffffffffu, sum_hi, 1);
    sum_hi += __shfl_xor_sync(0xffffffffu, sum_hi, 2);
    l_lo = l_lo * cor_lo + sum_lo;
    l_hi = l_hi * cor_hi + sum_hi;
    #pragma unroll
    for (int nf = 0; nf < 16; nf++) {
        o[nf][0] *= cor_lo; o[nf][1] *= cor_lo;
        o[nf][2] *= cor_hi; o[nf][3] *= cor_hi;
    }
    __syncthreads();

    // stage V^T (scatter halves); zero s-columns in [NFB*8, S32)
    const int S32 = (NFB >= 8) ? 64 : 32;
    #pragma unroll
    for (int j = 0; j < S32 / 16; j++) {
        int idx = tid + 256 * j;
        int ss = idx >> 4, ch = idx & 15;
        int og = bstart + ss;
        bool ok = (ss < NFB * 8) && og >= 0 && og < TT;
        uint4 v = ok ? *(const uint4*)(Vf + (size_t)og * HD + ch * 8) : make_uint4(0, 0, 0, 0);
        unsigned tmp[4] = {v.x, v.y, v.z, v.w};
        int G2 = ch >> 2, lcd = ch & 3;
        int sg_ = ss >> 5, sl = ss & 31;
        int p32 = ((sl >> 1) & 3) * 8 + ((sl >> 4) & 1) * 4 + ((sl >> 3) & 1) * 2 + (sl & 1);
        int chunkV = sg_ * 4 + (p32 >> 3);
        int inb = p32 & 7;
        #pragma unroll
        for (int i = 0; i < 8; i++) {
            int a = (i >> 2) & 1, bq = (i >> 1) & 1, dd = i & 1;
            int d = G2 * 32 + 16 * a + 8 * bq + 2 * lcd + dd;
            unsigned short hv = (unsigned short)((tmp[i >> 1] >> ((i & 1) * 16)) & 0xFFFF);
            *(unsigned short*)(VbC + d * 128 + swq(chunkV, d) * 16 + inb * 2) = hv;
        }
    }
    __syncthreads();

    #pragma unroll
    for (int G = 0; G < S32 / 32; G++) {
        int off = swq(G * 4 + lc, rloc) * 16;
        uint4 plo = *(const uint4*)(PsC + rloc * 128 + off);
        uint4 phi = *(const uint4*)(PsC + (rloc + 8) * 128 + off);
        int offv = swq(G * 4 + lc, r) * 16;
        #pragma unroll
        for (int nf = 0; nf < 16; nf++) {
            uint4 vv = *(const uint4*)(VbC + (nf * 8 + r) * 128 + offv);
            mma16(o[nf][0], o[nf][1], o[nf][2], o[nf][3],
                  plo.x, phi.x, plo.y, phi.y, vv.x, vv.y);
            mma16(o[nf][0], o[nf][1], o[nf][2], o[nf][3],
                  plo.z, phi.z, plo.w, phi.w, vv.z, vv.w);
        }
    }
    __syncthreads();
}

__global__ void __launch_bounds__(256, 2) attn_tc(const int* __restrict__ causal_p)
{
    extern __shared__ char sa[];
    char* QsC = sa + QS_OFF;
    char* KbC = sa + KB_OFF;
    char* VbC = sa + VB_OFF;
    char* PsC = sa + PS_OFF;

    int tid = threadIdx.x, lane = tid & 31, wid = tid >> 5;
    int h = blockIdx.z, b = blockIdx.y;
    int mt = (TT / 128 - 1) - blockIdx.x;       // reversed: big tiles first
    int m0 = mt * 128;
    size_t base = (size_t)(h * BB + b);
    const __half* Q   = g_q + base * TT * HD;
    const __half* Kf  = g_k + base * TT * HD;
    const __half* Vf  = g_v + base * TT * HD;
    const __half* Kc  = g_kc + base * CPAD * HD;
    const __half* VcT = g_vct + base * HD * CPAD;
    int causal = *causal_p;

    int s0, s1, s2, cnt;
    fano_lines(h, s0, s1, s2, cnt);

    int r = lane >> 2, lc = lane & 3;
    int rloc = wid * 16 + r;                    // 0..127
    int rowq = m0 + rloc;

    int nt_c;
    if (causal) {
        int x = m0 + 111;                       // (m0+127) - 16
        int qq = x / 7, rr = x % 7;
        int bound = 3 * qq + (s0 < rr) + (s1 < rr) + (s2 < rr);
        nt_c = (bound + 63) >> 6;
    } else {
        nt_c = CPAD / 64;
    }

    // prologue: stage Q (g0), K(0) (g1), V(0) (g2)
    #pragma unroll
    for (int j = 0; j < 8; j++) {
        int idx = tid + 256 * j;
        int row = idx >> 4, ch = idx & 15;
        cp16(QsC + row * 256 + swq(ch, row) * 16, Q + (size_t)(m0 + row) * HD + ch * 8);
    }
    cp_commit();
    #pragma unroll
    for (int j = 0; j < 4; j++) {
        int idx = tid + 256 * j;
        int nn = idx >> 4, ch = idx & 15;
        cp16(KbC + nn * 256 + swq(ch, nn) * 16, Kc + (size_t)nn * HD + ch * 8);
    }
    cp_commit();
    #pragma unroll
    for (int j = 0; j < 4; j++) {
        int idx = tid + 256 * j;
        int dd = idx >> 3, ch = idx & 7;
        cp16(VbC + dd * 128 + swq(ch, dd) * 16, VcT + (size_t)dd * CPAD + ch * 8);
    }
    cp_commit();

    float o[16][4];
    #pragma unroll
    for (int nf = 0; nf < 16; nf++)
        #pragma unroll
        for (int e = 0; e < 4; e++) o[nf][e] = 0.f;
    float m_lo = -1e30f, m_hi = -1e30f, l_lo = 0.f, l_hi = 0.f;

    // ---- compact phase (pipelined) ----
    for (int n = 0; n < nt_c; n++) {
        int n0 = n * 64;
        cp_wait<1>();           // Q + K(n) done
        __syncthreads();

        float s[8][4];
        #pragma unroll
        for (int nf = 0; nf < 8; nf++)
            #pragma unroll
            for (int e = 0; e < 4; e++) s[nf][e] = 0.f;
        #pragma unroll
        for (int G = 0; G < 4; G++) {
            int off = swq(G * 4 + lc, r) * 16;
            uint4 qlo = *(const uint4*)(QsC + rloc * 256 + off);
            uint4 qhi = *(const uint4*)(QsC + (rloc + 8) * 256 + off);
            #pragma unroll
            for (int nf = 0; nf < 8; nf++) {
                uint4 bb = *(const uint4*)(KbC + (nf * 8 + r) * 256 + off);
                mma16(s[nf][0], s[nf][1], s[nf][2], s[nf][3],
                      qlo.x, qhi.x, qlo.y, qhi.y, bb.x, bb.y);
                mma16(s[nf][0], s[nf][1], s[nf][2], s[nf][3],
                      qlo.z, qhi.z, qlo.w, qhi.w, bb.z, bb.w);
            }
        }
        __syncthreads();        // K reads done

        if (n + 1 < nt_c) {
            int n1 = (n + 1) * 64;
            #pragma unroll
            for (int j = 0; j < 4; j++) {
                int idx = tid + 256 * j;
                int nn = idx >> 4, ch = idx & 15;
                cp16(KbC + nn * 256 + swq(ch, nn) * 16, Kc + (size_t)(n1 + nn) * HD + ch * 8);
            }
        }
        cp_commit();

        // mask + online softmax
        float mx_lo = -1e30f, mx_hi = -1e30f;
        int gi_lo = rowq, gi_hi = rowq + 8;
        #pragma unroll
        for (int nf = 0; nf < 8; nf++) {
            #pragma unroll
            for (int t = 0; t < 2; t++) {
                int cj = n0 + nf * 8 + 2 * lc + t;
                int qq = cj / 3, uu = cj - 3 * qq;
                int sl = (uu == 0) ? s0 : ((uu == 1) ? s1 : s2);
                int og = 7 * qq + sl;
                bool ok_lo, ok_hi;
                if (causal) { ok_lo = og <= gi_lo - 17; ok_hi = og <= gi_hi - 17; }
                else {
                    bool inr = og < TT;
                    ok_lo = inr && (og <= gi_lo - 17 || og >= gi_lo + 17);
                    ok_hi = inr && (og <= gi_hi - 17 || og >= gi_hi + 17);
                }
                float vlo = ok_lo ? s[nf][t] * SCLC : -1e30f;
                float vhi = ok_hi ? s[nf][2 + t] * SCLC : -1e30f;
                s[nf][t] = vlo; s[nf][2 + t] = vhi;
                mx_lo = fmaxf(mx_lo, vlo); mx_hi = fmaxf(mx_hi, vhi);
            }
        }
        mx_lo = fmaxf(mx_lo, __shfl_xor_sync(0xffffffffu, mx_lo, 1));
        mx_lo = fmaxf(mx_lo, __shfl_xor_sync(0xffffffffu, mx_lo, 2));
        mx_hi = fmaxf(mx_hi, __shfl_xor_sync(0xffffffffu, mx_hi, 1));
        mx_hi = fmaxf(mx_hi, __shfl_xor_sync(0xffffffffu, mx_hi, 2));

        float mn_lo = fmaxf(fmaxf(m_lo, mx_lo), -1e28f);
        float mn_hi = fmaxf(fmaxf(m_hi, mx_hi), -1e28f);
        float cor_lo = exp2f(m_lo - mn_lo), cor_hi = exp2f(m_hi - mn_hi);
        m_lo = mn_lo; m_hi = mn_hi;

        float sum_lo = 0.f, sum_hi = 0.f;
        #pragma unroll
        for (int nf = 0; nf < 8; nf++) {
            float p0 = exp2f(s[nf][0] - mn_lo);
            float p1 = exp2f(s[nf][1] - mn_lo);
            float p2 = exp2f(s[nf][2] - mn_hi);
            float p3 = exp2f(s[nf][3] - mn_hi);
            sum_lo += p0 + p1; sum_hi += p2 + p3;
            int boff = swq((nf >> 2) * 4 + lc, rloc) * 16 + (((nf >> 1) & 1) * 4 + (nf & 1) * 2) * 2;
            *(__half2*)(PsC + rloc * 128 + boff)       = __floats2half2_rn(p0, p1);
            *(__half2*)(PsC + (rloc + 8) * 128 + boff) = __floats2half2_rn(p2, p3);
        }
        sum_lo += __shfl_xor_sync(0xffffffffu, sum_lo, 1);
        sum_lo += __shfl_xor_sync(0xffffffffu, sum_lo, 2);
        sum_hi += __shfl_xor_sync(0xffffffffu, sum_hi, 1);
        sum_hi += __shfl_xor_sync(0xffffffffu, sum_hi, 2);
        l_lo = l_lo * cor_lo + sum_lo;
        l_hi = l_hi * cor_hi + sum_hi;
        #pragma unroll
        for (int nf = 0; nf < 16; nf++) {
            o[nf][0] *= cor_lo; o[nf][1] *= cor_lo;
            o[nf][2] *= cor_hi; o[nf][3] *= cor_hi;
        }

        cp_wait<1>();           // V(n) done
        __syncthreads();        // V + Ps visible

        #pragma unroll
        for (int G = 0; G < 2; G++) {
            int off = swq(G * 4 + lc, rloc) * 16;
            uint4 plo = *(const uint4*)(PsC + rloc * 128 + off);
            uint4 phi = *(const uint4*)(PsC + (rloc + 8) * 128 + off);
            int offv = swq(G * 4 + lc, r) * 16;
            #pragma unroll
            for (int nf = 0; nf < 16; nf++) {
                uint4 vv = *(const uint4*)(VbC + (nf * 8 + r) * 128 + offv);
                mma16(o[nf][0], o[nf][1], o[nf][2], o[nf][3],
                      plo.x, phi.x, plo.y, phi.y, vv.x, vv.y);
                mma16(o[nf][0], o[nf][1], o[nf][2], o[nf][3],
                      plo.z, phi.z, plo.w, phi.w, vv.z, vv.w);
            }
        }
        __syncthreads();        // V + Ps reads done

        if (n + 1 < nt_c) {
            int n1 = (n + 1) * 64;
            #pragma unroll
            for (int j = 0; j < 4; j++) {
                int idx = tid + 256 * j;
                int dd = idx >> 3, ch = idx & 7;
                cp16(VbC + dd * 128 + swq(ch, dd) * 16, VcT + (size_t)dd * CPAD + n1 + ch * 8);
            }
        }
        cp_commit();
    }

    // ---- band tiles (3 for BM=128) ----
    band_tile<8>(m0 - 16, causal, Kf, Vf, QsC, KbC, VbC, PsC, o,
                 m_lo, m_hi, l_lo, l_hi, tid, r, lc, rloc, rowq);
    band_tile<8>(m0 + 48, causal, Kf, Vf, QsC, KbC, VbC, PsC, o,
                 m_lo, m_hi, l_lo, l_hi, tid, r, lc, rloc, rowq);
    if (causal)
        band_tile<2>(m0 + 112, 1, Kf, Vf, QsC, KbC, VbC, PsC, o,
                     m_lo, m_hi, l_lo, l_hi, tid, r, lc, rloc, rowq);
    else
        band_tile<4>(m0 + 112, 0, Kf, Vf, QsC, KbC, VbC, PsC, o,
                     m_lo, m_hi, l_lo, l_hi, tid, r, lc, rloc, rowq);

    // epilogue: normalize, fp16, perm32 concatenated-head layout
    float inv_lo = 1.f / l_lo, inv_hi = 1.f / l_hi;
    __half* OPl = g_att + ((size_t)b * TT + rowq) * HID + h * HD;
    __half* OPh = g_att + ((size_t)b * TT + rowq + 8) * HID + h * HD;
    #pragma unroll
    for (int nf = 0; nf < 16; nf++) {
        int cb = (nf >> 2) * 32 + lc * 8 + ((nf >> 1) & 1) * 4 + (nf & 1) * 2;
        *(__half2*)&OPl[cb] = __floats2half2_rn(o[nf][0] * inv_lo, o[nf][1] * inv_lo);
        *(__half2*)&OPh[cb] = __floats2half2_rn(o[nf][2] * inv_hi, o[nf][3] * inv_hi);
    }
}

// ---------------------------------------------------------------------------
extern "C" void kernel_launch(void* const* d_in, const int* in_sizes, int n_in,
                              void* d_out, int out_size)
{
    const float* x  = (const float*)d_in[0];
    const float* Wq = (const float*)d_in[1];
    const float* Wk = (const float*)d_in[2];
    const float* Wv = (const float*)d_in[3];
    const float* Wo = (const float*)d_in[4];
    const int* isc  = (const int*)d_in[5];
    float* out = (float*)d_out;

    cudaFuncSetAttribute(proj_tc, cudaFuncAttributeMaxDynamicSharedMemorySize, GSMEM);
    cudaFuncSetAttribute(outproj_tc, cudaFuncAttributeMaxDynamicSharedMemorySize, GSMEM);
    cudaFuncSetAttribute(attn_tc, cudaFuncAttributeMaxDynamicSharedMemorySize, ATTN_SM);

    __half* d_xt;  cudaGetSymbolAddress((void**)&d_xt, g_xt);
    __half* d_wot; cudaGetSymbolAddress((void**)&d_wot, g_wot);

    prep_perm<<<(MTOT * HID / 32 + 255) / 256, 256>>>(x, d_xt, MTOT * HID / 32);
    prep_perm<<<(HID * HID / 32 + 255) / 256, 256>>>(Wo, d_wot, HID * HID / 32);
    prep_wt<<<dim3(HID / 32, HD / 32, 21), dim3(32, 8)>>>(Wq, Wk, Wv);

    proj_tc<<<dim3(MTOT / 128, 21), 128, GSMEM>>>();
    compact_k<<<dim3(CPAD / 64, NH * BB), 256>>>();
    compact_vT<<<dim3(CPAD / 32, HD / 32, NH * BB), dim3(32, 8)>>>();
    attn_tc<<<dim3(TT / 128, BB, NH), 256, ATTN_SM>>>(isc);
    outproj_tc<<<dim3(MTOT / 128, HID / 128), 128, GSMEM>>>(out);
}

// round 17
// speedup vs baseline: 1.1683x; 1.1683x over previous
#include <cuda_runtime.h>
#include <cuda_fp16.h>
#include <cstdint>

#define NH    7
#define HD    128
#define BB    4
#define TT    2048
#define HID   896
#define MTOT  (BB*TT)   // 8192
#define CPAD  896       // padded compact length (>= max 879, multiple of 64)

#define SCLC (0.08838834764831845f * 1.4426950408889634f)  // 1/sqrt(128)*log2(e)

// Scratch (allocation-free rule: __device__ globals).  All MMA operands fp16,
// stored k-permuted in 32-groups: chunk lc (8 halves) holds k =
// {2lc,2lc+1, 2lc+8,2lc+9, 2lc+16,2lc+17, 2lc+24,2lc+25}.
// g_q is PRE-SCALED by SCLC (folded into proj epilogue).
__device__ __half g_xt[(size_t)MTOT * HID];
__device__ __half g_wt[(size_t)21 * HD * HID];
__device__ __half g_wot[(size_t)HID * HID];
__device__ __half g_q[(size_t)NH * MTOT * HD];
__device__ __half g_k[(size_t)NH * MTOT * HD];
__device__ __half g_v[(size_t)NH * MTOT * HD];
__device__ __half g_kc[(size_t)NH * BB * CPAD * HD];   // compacted K [slot][d perm]
__device__ __half g_vct[(size_t)NH * BB * HD * CPAD];  // compacted V^T [d][perm(slot)]
__device__ __half g_att[(size_t)MTOT * HID];

__device__ __forceinline__ void mma16(float& d0, float& d1, float& d2, float& d3,
                                      unsigned a0, unsigned a1, unsigned a2, unsigned a3,
                                      unsigned b0, unsigned b1) {
    asm volatile(
        "mma.sync.aligned.m16n8k16.row.col.f32.f16.f16.f32 "
        "{%0,%1,%2,%3}, {%4,%5,%6,%7}, {%8,%9}, {%0,%1,%2,%3};\n"
        : "+f"(d0), "+f"(d1), "+f"(d2), "+f"(d3)
        : "r"(a0), "r"(a1), "r"(a2), "r"(a3), "r"(b0), "r"(b1));
}

// conflict-free 16B-chunk swizzle: XOR low 3 bits with perm(row)
__device__ __forceinline__ int permq(int row) { return ((row & 1) << 2) | ((row >> 1) & 3); }
__device__ __forceinline__ int swq(int lch, int row) {
    return (lch & ~7) | ((lch & 7) ^ permq(row));
}

__device__ __forceinline__ void cp16(void* dst, const void* src) {
    unsigned d = (unsigned)__cvta_generic_to_shared(dst);
    asm volatile("cp.async.cg.shared.global [%0], [%1], 16;" :: "r"(d), "l"(src));
}
__device__ __forceinline__ void cp_commit() { asm volatile("cp.async.commit_group;"); }
template<int N> __device__ __forceinline__ void cp_wait() {
    asm volatile("cp.async.wait_group %0;" :: "n"(N));
}

// ===========================================================================
// Prep kernels: fp16 conversion + 32-wide k-perm
// ===========================================================================
__global__ void prep_perm(const float* __restrict__ src, __half* __restrict__ dst, int total32)
{
    int t = blockIdx.x * 256 + threadIdx.x;
    if (t >= total32) return;
    const float* s = src + (size_t)t * 32;
    float in[32];
    #pragma unroll
    for (int i = 0; i < 8; i++) {
        float4 v = ((const float4*)s)[i];
        in[4*i] = v.x; in[4*i+1] = v.y; in[4*i+2] = v.z; in[4*i+3] = v.w;
    }
    __half2* d = (__half2*)(dst + (size_t)t * 32);
    #pragma unroll
    for (int lc = 0; lc < 4; lc++) {
        d[lc*4 + 0] = __floats2half2_rn(in[2*lc],      in[2*lc + 1]);
        d[lc*4 + 1] = __floats2half2_rn(in[2*lc + 8],  in[2*lc + 9]);
        d[lc*4 + 2] = __floats2half2_rn(in[2*lc + 16], in[2*lc + 17]);
        d[lc*4 + 3] = __floats2half2_rn(in[2*lc + 24], in[2*lc + 25]);
    }
}

// W[h][896][128] -> g_wt[z][n][896] transposed + perm32
__global__ void prep_wt(const float* __restrict__ Wq, const float* __restrict__ Wk,
                        const float* __restrict__ Wv)
{
    __shared__ float tb[32][33];
    int z = blockIdx.z, h = z / 3, sel = z % 3;
    const float* W = (sel == 0 ? Wq : (sel == 1 ? Wk : Wv)) + (size_t)h * HID * HD;
    int k0 = blockIdx.x * 32, n0 = blockIdx.y * 32;
    int tx = threadIdx.x, ty = threadIdx.y;
    #pragma unroll
    for (int i = 0; i < 4; i++)
        tb[ty + 8 * i][tx] = W[(size_t)(k0 + ty + 8 * i) * HD + n0 + tx];
    __syncthreads();
    int al = 16 * ((tx >> 2) & 1) + 8 * ((tx >> 1) & 1) + 2 * (tx >> 3) + (tx & 1);
    #pragma unroll
    for (int i = 0; i < 4; i++) {
        int n = n0 + ty + 8 * i;
        g_wt[((size_t)z * HD + n) * HID + k0 + tx] = __float2half_rn(tb[al][ty + 8 * i]);
    }
}

__device__ __forceinline__ void fano_lines(int h, int& s0, int& s1, int& s2, int& cnt)
{
    int t;
    s0 = h; s1 = (h + 1) % 7; s2 = (h + 3) % 7;
    if (s0 > s1) { t = s0; s0 = s1; s1 = t; }
    if (s1 > s2) { t = s1; s1 = s2; s2 = t; }
    if (s0 > s1) { t = s0; s0 = s1; s1 = t; }
    cnt = 3 * 292 + (s0 < 4) + (s1 < 4) + (s2 < 4);
}

// compact index -> original column (monotone in c since s0<s1<s2)
__device__ __forceinline__ int cmap(int c, int s0, int s1, int s2)
{
    int q = c / 3, u = c - 3 * q;
    int sl = (u == 0) ? s0 : ((u == 1) ? s1 : s2);
    return 7 * q + sl;
}

__global__ void __launch_bounds__(256) compact_k()
{
    int h = blockIdx.y >> 2, b = blockIdx.y & 3;
    int tid = threadIdx.x;
    int c = blockIdx.x * 64 + (tid >> 2);
    int seg = tid & 3;
    int s0, s1, s2, cnt;
    fano_lines(h, s0, s1, s2, cnt);
    int o = cmap(c, s0, s1, s2);
    bool valid = c < cnt;
    size_t sb = ((size_t)(h * BB + b) * TT + o) * HD + seg * 32;
    size_t db = ((size_t)(h * BB + b) * CPAD + c) * HD + seg * 32;
    uint4 z4 = make_uint4(0, 0, 0, 0);
    #pragma unroll
    for (int i = 0; i < 4; i++)
        *(uint4*)&g_kc[db + i * 8] = valid ? *(const uint4*)&g_k[sb + i * 8] : z4;
}

// V compaction + transpose: g_vct[d][c0 + pos32(c_local)] = V[slot(c)][d]
__global__ void compact_vT()   // grid (CPAD/32, HD/32, 28), block (32, 8)
{
    __shared__ __half tb[32][33];
    int z = blockIdx.z, h = z >> 2, b = z & 3;
    int s0, s1, s2, cnt;
    fano_lines(h, s0, s1, s2, cnt);
    int c0 = blockIdx.x * 32, d0 = blockIdx.y * 32;
    int tx = threadIdx.x, ty = threadIdx.y;
    const __half* Vsrc = g_v + (size_t)(h * BB + b) * TT * HD;
    size_t dstb = (size_t)(h * BB + b) * HD * CPAD;
    int al = 16 * ((tx >> 2) & 1) + 8 * ((tx >> 1) & 1) + 2 * (tx >> 3) + (tx & 1);
    #pragma unroll
    for (int i = 0; i < 4; i++) {
        int c = c0 + ty + 8 * i;
        int og = cmap(c, s0, s1, s2);
        __half val = (c < cnt) ? Vsrc[(size_t)og * HD + d0 + tx] : __float2half(0.f);
        tb[ty + 8 * i][al] = val;
    }
    __syncthreads();
    int destc = c0 + ((tx >> 1) & 3) * 8 + ((tx >> 4) & 1) * 4 + ((tx >> 3) & 1) * 2 + (tx & 1);
    #pragma unroll
    for (int i = 0; i < 4; i++) {
        int d = d0 + ty + 8 * i;
        g_vct[dstb + (size_t)d * CPAD + destc] = tb[tx][ty + 8 * i];
    }
}

// ===========================================================================
// fp16 GEMM: 128x128 CTA, 4 warps 64x64, BK=64, 3-stage cp.async ring.
// PERM epilogue applies a uniform scale (SCLC for Q slices) before rounding.
// ===========================================================================
#define GSMEM 98304

__device__ __forceinline__ void gemm_issue(const __half* __restrict__ A,
                                           const __half* __restrict__ B,
                                           char* As, char* Bs,
                                           int kb, int m0, int n0, int tid)
{
    #pragma unroll
    for (int j = 0; j < 8; j++) {
        int idx = tid + 128 * j;
        int row = idx >> 3, ch = idx & 7;
        cp16(As + row * 128 + swq(ch, row) * 16, A + (size_t)(m0 + row) * HID + kb * 64 + ch * 8);
    }
    #pragma unroll
    for (int j = 0; j < 8; j++) {
        int idx = tid + 128 * j;
        int row = idx >> 3, ch = idx & 7;
        cp16(Bs + row * 128 + swq(ch, row) * 16, B + (size_t)(n0 + row) * HID + kb * 64 + ch * 8);
    }
    cp_commit();
}

template<bool PERM>
__device__ __forceinline__ void gemm_main(const __half* __restrict__ A,
                                          const __half* __restrict__ B,
                                          void* Cv, int ldc, int m0, int n0, float scale)
{
    extern __shared__ char sg[];
    int tid = threadIdx.x, lane = tid & 31, wid = tid >> 5;
    int wm = (wid >> 1) * 64, wn = (wid & 1) * 64;
    int r = lane >> 2, lc = lane & 3;

    float acc[4][8][4];
    #pragma unroll
    for (int f = 0; f < 4; f++)
        #pragma unroll
        for (int nf = 0; nf < 8; nf++)
            #pragma unroll
            for (int e = 0; e < 4; e++) acc[f][nf][e] = 0.f;

    gemm_issue(A, B, sg,         sg + 16384,         0, m0, n0, tid);
    gemm_issue(A, B, sg + 32768, sg + 32768 + 16384, 1, m0, n0, tid);

    #pragma unroll 1
    for (int kb = 0; kb < 14; kb++) {
        int st = kb % 3;
        char* As = sg + st * 32768;
        char* Bs = As + 16384;
        cp_wait<1>();
        __syncthreads();
        #pragma unroll
        for (int G = 0; G < 2; G++) {
            int off = swq(G * 4 + lc, r) * 16;
            uint4 alo[4], ahi[4];
            #pragma unroll
            for (int mf = 0; mf < 4; mf++) {
                int row = wm + mf * 16 + r;
                alo[mf] = *(const uint4*)(As + row * 128 + off);
                ahi[mf] = *(const uint4*)(As + (row + 8) * 128 + off);
            }
            uint4 bb[8];
            #pragma unroll
            for (int nf = 0; nf < 8; nf++)
                bb[nf] = *(const uint4*)(Bs + (wn + nf * 8 + r) * 128 + off);
            #pragma unroll
            for (int mf = 0; mf < 4; mf++)
                #pragma unroll
                for (int nf = 0; nf < 8; nf++) {
                    mma16(acc[mf][nf][0], acc[mf][nf][1], acc[mf][nf][2], acc[mf][nf][3],
                          alo[mf].x, ahi[mf].x, alo[mf].y, ahi[mf].y, bb[nf].x, bb[nf].y);
                    mma16(acc[mf][nf][0], acc[mf][nf][1], acc[mf][nf][2], acc[mf][nf][3],
                          alo[mf].z, ahi[mf].z, alo[mf].w, ahi[mf].w, bb[nf].z, bb[nf].w);
                }
        }
        if (kb + 2 < 14) {
            int ns = (kb + 2) % 3;
            gemm_issue(A, B, sg + ns * 32768, sg + ns * 32768 + 16384, kb + 2, m0, n0, tid);
        } else {
            cp_commit();
        }
    }

    #pragma unroll
    for (int mf = 0; mf < 4; mf++) {
        int row = m0 + wm + mf * 16 + r;
        #pragma unroll
        for (int nf = 0; nf < 8; nf++) {
            if (PERM) {
                __half* C = (__half*)Cv;
                int cb = n0 + wn + (nf >> 2) * 32 + lc * 8 + ((nf >> 1) & 1) * 4 + (nf & 1) * 2;
                *(__half2*)&C[(size_t)row * ldc + cb] =
                    __floats2half2_rn(acc[mf][nf][0] * scale, acc[mf][nf][1] * scale);
                *(__half2*)&C[(size_t)(row + 8) * ldc + cb] =
                    __floats2half2_rn(acc[mf][nf][2] * scale, acc[mf][nf][3] * scale);
            } else {
                float* C = (float*)Cv;
                int cb = n0 + wn + nf * 8 + 2 * lc;
                *(float2*)&C[(size_t)row * ldc + cb] =
                    make_float2(acc[mf][nf][0], acc[mf][nf][1]);
                *(float2*)&C[(size_t)(row + 8) * ldc + cb] =
                    make_float2(acc[mf][nf][2], acc[mf][nf][3]);
            }
        }
    }
}

__global__ void __launch_bounds__(128, 2) proj_tc()
{
    int z = blockIdx.y;
    __half* out = ((z % 3) == 0 ? g_q : ((z % 3) == 1 ? g_k : g_v)) + (size_t)(z / 3) * MTOT * HD;
    float scale = ((z % 3) == 0) ? SCLC : 1.f;   // pre-scale Q for softmax
    gemm_main<true>(g_xt, g_wt + (size_t)z * HD * HID, out, HD, blockIdx.x * 128, 0, scale);
}

__global__ void __launch_bounds__(128, 2) outproj_tc(float* __restrict__ out)
{
    gemm_main<false>(g_att, g_wot, out, HID, blockIdx.x * 128, blockIdx.y * 128, 1.f);
}

// ===========================================================================
// fp16 flash attention, BM=64 (R14 champion) + uniform full-valid fast path.
// Q pre-scaled by SCLC, so no scale multiplies here.
// ===========================================================================
#define KB_OFF 0
#define VB_OFF 16384
#define PS_OFF 32768
#define ATTN_SM 40960

template<int NFB>
__device__ __forceinline__ void band_tile(
    int bstart, int causal,
    const __half* __restrict__ Kf, const __half* __restrict__ Vf,
    char* KbC, char* VbC, char* PsC,
    const unsigned (&qf)[8][4], float (&o)[16][4],
    float& m_lo, float& m_hi, float& l_lo, float& l_hi,
    int tid, int r, int lc, int rloc, int rowq)
{
    // stage K rows [bstart, bstart+8*NFB)
    #pragma unroll
    for (int j = 0; j < NFB; j++) {
        int idx = tid + 128 * j;
        int nn = idx >> 4, ch = idx & 15;
        int og = bstart + nn;
        uint4 v = (og >= 0 && og < TT)
            ? *(const uint4*)(Kf + (size_t)og * HD + ch * 8)
            : make_uint4(0, 0, 0, 0);
        *(uint4*)(KbC + nn * 256 + swq(ch, nn) * 16) = v;
    }
    __syncthreads();

    float s[NFB][4];
    #pragma unroll
    for (int nf = 0; nf < NFB; nf++)
        #pragma unroll
        for (int e = 0; e < 4; e++) s[nf][e] = 0.f;
    #pragma unroll
    for (int G = 0; G < 4; G++) {
        int off = swq(G * 4 + lc, r) * 16;
        #pragma unroll
        for (int nf = 0; nf < NFB; nf++) {
            uint4 bb = *(const uint4*)(KbC + (nf * 8 + r) * 256 + off);
            mma16(s[nf][0], s[nf][1], s[nf][2], s[nf][3],
                  qf[2*G][0], qf[2*G][1], qf[2*G][2], qf[2*G][3], bb.x, bb.y);
            mma16(s[nf][0], s[nf][1], s[nf][2], s[nf][3],
                  qf[2*G+1][0], qf[2*G+1][1], qf[2*G+1][2], qf[2*G+1][3], bb.z, bb.w);
        }
    }

    float mx_lo = -1e30f, mx_hi = -1e30f;
    int gi_lo = rowq, gi_hi = rowq + 8;
    #pragma unroll
    for (int nf = 0; nf < NFB; nf++) {
        #pragma unroll
        for (int t = 0; t < 2; t++) {
            int og = bstart + nf * 8 + 2 * lc + t;
            bool ok_lo, ok_hi;
            if (causal) {
                ok_lo = (og >= gi_lo - 16) && (og <= gi_lo) && (og >= 0);
                ok_hi = (og >= gi_hi - 16) && (og <= gi_hi) && (og >= 0);
            } else {
                bool inr = (og >= 0) && (og < TT);
                ok_lo = inr && (og >= gi_lo - 16) && (og <= gi_lo + 16);
                ok_hi = inr && (og >= gi_hi - 16) && (og <= gi_hi + 16);
            }
            float vlo = ok_lo ? s[nf][t] : -1e30f;
            float vhi = ok_hi ? s[nf][2 + t] : -1e30f;
            s[nf][t] = vlo; s[nf][2 + t] = vhi;
            mx_lo = fmaxf(mx_lo, vlo); mx_hi = fmaxf(mx_hi, vhi);
        }
    }
    mx_lo = fmaxf(mx_lo, __shfl_xor_sync(0xffffffffu, mx_lo, 1));
    mx_lo = fmaxf(mx_lo, __shfl_xor_sync(0xffffffffu, mx_lo, 2));
    mx_hi = fmaxf(mx_hi, __shfl_xor_sync(0xffffffffu, mx_hi, 1));
    mx_hi = fmaxf(mx_hi, __shfl_xor_sync(0xffffffffu, mx_hi, 2));

    float mn_lo = fmaxf(fmaxf(m_lo, mx_lo), -1e28f);
    float mn_hi = fmaxf(fmaxf(m_hi, mx_hi), -1e28f);
    float cor_lo = exp2f(m_lo - mn_lo), cor_hi = exp2f(m_hi - mn_hi);
    m_lo = mn_lo; m_hi = mn_hi;

    float sum_lo = 0.f, sum_hi = 0.f;
    #pragma unroll
    for (int nf = 0; nf < NFB; nf++) {
        float p0 = exp2f(s[nf][0] - mn_lo);
        float p1 = exp2f(s[nf][1] - mn_lo);
        float p2 = exp2f(s[nf][2] - mn_hi);
        float p3 = exp2f(s[nf][3] - mn_hi);
        sum_lo += p0 + p1; sum_hi += p2 + p3;
        int boff = swq((nf >> 2) * 4 + lc, rloc) * 16 + (((nf >> 1) & 1) * 4 + (nf & 1) * 2) * 2;
        *(__half2*)(PsC + rloc * 128 + boff)       = __floats2half2_rn(p0, p1);
        *(__half2*)(PsC + (rloc + 8) * 128 + boff) = __floats2half2_rn(p2, p3);
    }
    sum_lo += __shfl_xor_sync(0xffffffffu, sum_lo, 1);
    sum_lo += __shfl_xor_sync(0xffffffffu, sum_lo, 2);
    sum_hi += __shfl_xor_sync(0xffffffffu, sum_hi, 1);
    sum_hi += __shfl_xor_sync(0xffffffffu, sum_hi, 2);
    l_lo = l_lo * cor_lo + sum_lo;
    l_hi = l_hi * cor_hi + sum_hi;
    #pragma unroll
    for (int nf = 0; nf < 16; nf++) {
        o[nf][0] *= cor_lo; o[nf][1] *= cor_lo;
        o[nf][2] *= cor_hi; o[nf][3] *= cor_hi;
    }
    __syncthreads();

    // stage V^T (scatter halves); zero s-columns in [NFB*8, S32)
    const int S32 = (NFB >= 8) ? 64 : 32;
    #pragma unroll
    for (int j = 0; j < S32 / 8; j++) {
        int idx = tid + 128 * j;
        int ss = idx >> 4, ch = idx & 15;
        int og = bstart + ss;
        bool ok = (ss < NFB * 8) && og >= 0 && og < TT;
        uint4 v = ok ? *(const uint4*)(Vf + (size_t)og * HD + ch * 8) : make_uint4(0, 0, 0, 0);
        unsigned tmp[4] = {v.x, v.y, v.z, v.w};
        int G2 = ch >> 2, lcd = ch & 3;
        int sg_ = ss >> 5, sl = ss & 31;
        int p32 = ((sl >> 1) & 3) * 8 + ((sl >> 4) & 1) * 4 + ((sl >> 3) & 1) * 2 + (sl & 1);
        int chunkV = sg_ * 4 + (p32 >> 3);
        int inb = p32 & 7;
        #pragma unroll
        for (int i = 0; i < 8; i++) {
            int a = (i >> 2) & 1, bq = (i >> 1) & 1, dd = i & 1;
            int d = G2 * 32 + 16 * a + 8 * bq + 2 * lcd + dd;
            unsigned short hv = (unsigned short)((tmp[i >> 1] >> ((i & 1) * 16)) & 0xFFFF);
            *(unsigned short*)(VbC + d * 128 + swq(chunkV, d) * 16 + inb * 2) = hv;
        }
    }
    __syncthreads();

    #pragma unroll
    for (int G = 0; G < S32 / 32; G++) {
        int off = swq(G * 4 + lc, rloc) * 16;
        uint4 plo = *(const uint4*)(PsC + rloc * 128 + off);
        uint4 phi = *(const uint4*)(PsC + (rloc + 8) * 128 + off);
        int offv = swq(G * 4 + lc, r) * 16;
        #pragma unroll
        for (int nf = 0; nf < 16; nf++) {
            uint4 vv = *(const uint4*)(VbC + (nf * 8 + r) * 128 + offv);
            mma16(o[nf][0], o[nf][1], o[nf][2], o[nf][3],
                  plo.x, phi.x, plo.y, phi.y, vv.x, vv.y);
            mma16(o[nf][0], o[nf][1], o[nf][2], o[nf][3],
                  plo.z, phi.z, plo.w, phi.w, vv.z, vv.w);
        }
    }
    __syncthreads();
}

__global__ void __launch_bounds__(128, 3) attn_tc(const int* __restrict__ causal_p)
{
    extern __shared__ char sa[];
    char* KbC = sa + KB_OFF;
    char* VbC = sa + VB_OFF;
    char* PsC = sa + PS_OFF;

    int tid = threadIdx.x, lane = tid & 31, wid = tid >> 5;
    int h = blockIdx.z, b = blockIdx.y;
    int mt = (TT / 64 - 1) - blockIdx.x;        // reversed: big tiles first
    int m0 = mt * 64;
    size_t base = (size_t)(h * BB + b);
    const __half* Q   = g_q + base * TT * HD;
    const __half* Kf  = g_k + base * TT * HD;
    const __half* Vf  = g_v + base * TT * HD;
    const __half* Kc  = g_kc + base * CPAD * HD;
    const __half* VcT = g_vct + base * HD * CPAD;
    int causal = *causal_p;

    int s0, s1, s2, cnt;
    fano_lines(h, s0, s1, s2, cnt);

    int r = lane >> 2, lc = lane & 3;
    int rowq = m0 + wid * 16 + r;
    int rloc = wid * 16 + r;

    int nt_c;
    if (causal) {
        int x = m0 + 47;
        int qq = x / 7, rr = x % 7;
        int bound = 3 * qq + (s0 < rr) + (s1 < rr) + (s2 < rr);
        nt_c = (bound + 63) >> 6;
    } else {
        nt_c = CPAD / 64;
    }

    // prologue: K(0), V(0)
    #pragma unroll
    for (int j = 0; j < 8; j++) {
        int idx = tid + 128 * j;
        int nn = idx >> 4, ch = idx & 15;
        cp16(KbC + nn * 256 + swq(ch, nn) * 16, Kc + (size_t)nn * HD + ch * 8);
    }
    cp_commit();
    #pragma unroll
    for (int j = 0; j < 8; j++) {
        int idx = tid + 128 * j;
        int dd = idx >> 3, ch = idx & 7;
        cp16(VbC + dd * 128 + swq(ch, dd) * 16, VcT + (size_t)dd * CPAD + ch * 8);
    }
    cp_commit();

    // Q fragments (pre-scaled by SCLC): one uint4 per (row-half, G) = 2 k16 blocks
    unsigned qf[8][4];
    #pragma unroll
    for (int G = 0; G < 4; G++) {
        uint4 rlo = ((const uint4*)(Q + (size_t)rowq * HD))[G * 4 + lc];
        uint4 rhi = ((const uint4*)(Q + (size_t)(rowq + 8) * HD))[G * 4 + lc];
        qf[2*G][0] = rlo.x; qf[2*G][1] = rhi.x; qf[2*G][2] = rlo.y; qf[2*G][3] = rhi.y;
        qf[2*G+1][0] = rlo.z; qf[2*G+1][1] = rhi.z; qf[2*G+1][2] = rlo.w; qf[2*G+1][3] = rhi.w;
    }

    float o[16][4];
    #pragma unroll
    for (int nf = 0; nf < 16; nf++)
        #pragma unroll
        for (int e = 0; e < 4; e++) o[nf][e] = 0.f;
    float m_lo = -1e30f, m_hi = -1e30f, l_lo = 0.f, l_hi = 0.f;

    // ---- compact phase (pipelined) ----
    for (int n = 0; n < nt_c; n++) {
        int n0 = n * 64;
        cp_wait<1>();           // K(n)
        __syncthreads();

        float s[8][4];
        #pragma unroll
        for (int nf = 0; nf < 8; nf++)
            #pragma unroll
            for (int e = 0; e < 4; e++) s[nf][e] = 0.f;
        #pragma unroll
        for (int G = 0; G < 4; G++) {
            int off = swq(G * 4 + lc, r) * 16;
            #pragma unroll
            for (int nf = 0; nf < 8; nf++) {
                uint4 bb = *(const uint4*)(KbC + (nf * 8 + r) * 256 + off);
                mma16(s[nf][0], s[nf][1], s[nf][2], s[nf][3],
                      qf[2*G][0], qf[2*G][1], qf[2*G][2], qf[2*G][3], bb.x, bb.y);
                mma16(s[nf][0], s[nf][1], s[nf][2], s[nf][3],
                      qf[2*G+1][0], qf[2*G+1][1], qf[2*G+1][2], qf[2*G+1][3], bb.z, bb.w);
            }
        }
        __syncthreads();        // K reads done

        if (n + 1 < nt_c) {
            int n1 = (n + 1) * 64;
            #pragma unroll
            for (int j = 0; j < 8; j++) {
                int idx = tid + 128 * j;
                int nn = idx >> 4, ch = idx & 15;
                cp16(KbC + nn * 256 + swq(ch, nn) * 16, Kc + (size_t)(n1 + nn) * HD + ch * 8);
            }
        }
        cp_commit();

        // uniform full-valid check (og monotone in compact index)
        int og_min = cmap(n0, s0, s1, s2);
        int og_max = cmap(n0 + 63, s0, s1, s2);
        bool fullvalid = causal
            ? (og_max <= m0 - 17)
            : ((og_max <= m0 - 17) || (og_min >= m0 + 63 + 17 && og_max < TT));

        float mx_lo = -1e30f, mx_hi = -1e30f;
        if (fullvalid) {
            // fast path: no masking, S already scaled (Q pre-scaled)
            #pragma unroll
            for (int nf = 0; nf < 8; nf++) {
                mx_lo = fmaxf(mx_lo, fmaxf(s[nf][0], s[nf][1]));
                mx_hi = fmaxf(mx_hi, fmaxf(s[nf][2], s[nf][3]));
            }
        } else {
            int gi_lo = rowq, gi_hi = rowq + 8;
            #pragma unroll
            for (int nf = 0; nf < 8; nf++) {
                #pragma unroll
                for (int t = 0; t < 2; t++) {
                    int cj = n0 + nf * 8 + 2 * lc + t;
                    int og = cmap(cj, s0, s1, s2);
                    bool ok_lo, ok_hi;
                    if (causal) { ok_lo = og <= gi_lo - 17; ok_hi = og <= gi_hi - 17; }
                    else {
                        bool inr = og < TT;
                        ok_lo = inr && (og <= gi_lo - 17 || og >= gi_lo + 17);
                        ok_hi = inr && (og <= gi_hi - 17 || og >= gi_hi + 17);
                    }
                    float vlo = ok_lo ? s[nf][t] : -1e30f;
                    float vhi = ok_hi ? s[nf][2 + t] : -1e30f;
                    s[nf][t] = vlo; s[nf][2 + t] = vhi;
                    mx_lo = fmaxf(mx_lo, vlo); mx_hi = fmaxf(mx_hi, vhi);
                }
            }
        }
        mx_lo = fmaxf(mx_lo, __shfl_xor_sync(0xffffffffu, mx_lo, 1));
        mx_lo = fmaxf(mx_lo, __shfl_xor_sync(0xffffffffu, mx_lo, 2));
        mx_hi = fmaxf(mx_hi, __shfl_xor_sync(0xffffffffu, mx_hi, 1));
        mx_hi = fmaxf(mx_hi, __shfl_xor_sync(0xffffffffu, mx_hi, 2));

        float mn_lo = fmaxf(fmaxf(m_lo, mx_lo), -1e28f);
        float mn_hi = fmaxf(fmaxf(m_hi, mx_hi), -1e28f);
        float cor_lo = exp2f(m_lo - mn_lo), cor_hi = exp2f(m_hi - mn_hi);
        m_lo = mn_lo; m_hi = mn_hi;

        float sum_lo = 0.f, sum_hi = 0.f;
        #pragma unroll
        for (int nf = 0; nf < 8; nf++) {
            float p0 = exp2f(s[nf][0] - mn_lo);
            float p1 = exp2f(s[nf][1] - mn_lo);
            float p2 = exp2f(s[nf][2] - mn_hi);
            float p3 = exp2f(s[nf][3] - mn_hi);
            sum_lo += p0 + p1; sum_hi += p2 + p3;
            int boff = swq((nf >> 2) * 4 + lc, rloc) * 16 + (((nf >> 1) & 1) * 4 + (nf & 1) * 2) * 2;
            *(__half2*)(PsC + rloc * 128 + boff)       = __floats2half2_rn(p0, p1);
            *(__half2*)(PsC + (rloc + 8) * 128 + boff) = __floats2half2_rn(p2, p3);
        }
        sum_lo += __shfl_xor_sync(0xffffffffu, sum_lo, 1);
        sum_lo += __shfl_xor_sync(0xffffffffu, sum_lo, 2);
        sum_hi += __shfl_xor_sync(0xffffffffu, sum_hi, 1);
        sum_hi += __shfl_xor_sync(0xffffffffu, sum_hi, 2);
        l_lo = l_lo * cor_lo + sum_lo;
        l_hi = l_hi * cor_hi + sum_hi;
        #pragma unroll
        for (int nf = 0; nf < 16; nf++) {
            o[nf][0] *= cor_lo; o[nf][1] *= cor_lo;
            o[nf][2] *= cor_hi; o[nf][3] *= cor_hi;
        }

        cp_wait<1>();           // V(n)
        __syncthreads();        // V + Ps visible

        #pragma unroll
        for (int G = 0; G < 2; G++) {
            int off = swq(G * 4 + lc, rloc) * 16;
            uint4 plo = *(const uint4*)(PsC + rloc * 128 + off);
            uint4 phi = *(const uint4*)(PsC + (rloc + 8) * 128 + off);
            int offv = swq(G * 4 + lc, r) * 16;
            #pragma unroll
            for (int nf = 0; nf < 16; nf++) {
                uint4 vv = *(const uint4*)(VbC + (nf * 8 + r) * 128 + offv);
                mma16(o[nf][0], o[nf][1], o[nf][2], o[nf][3],
                      plo.x, phi.x, plo.y, phi.y, vv.x, vv.y);
                mma16(o[nf][0], o[nf][1], o[nf][2], o[nf][3],
                      plo.z, phi.z, plo.w, phi.w, vv.z, vv.w);
            }
        }
        __syncthreads();        // V + Ps reads done

        if (n + 1 < nt_c) {
            int n1 = (n + 1) * 64;
            #pragma unroll
            for (int j = 0; j < 8; j++) {
                int idx = tid + 128 * j;
                int dd = idx >> 3, ch = idx & 7;
                cp16(VbC + dd * 128 + swq(ch, dd) * 16, VcT + (size_t)dd * CPAD + n1 + ch * 8);
            }
        }
        cp_commit();
    }

    // ---- band tiles ----
    band_tile<8>(m0 - 16, causal, Kf, Vf, KbC, VbC, PsC, qf, o,
                 m_lo, m_hi, l_lo, l_hi, tid, r, lc, rloc, rowq);
    if (causal)
        band_tile<2>(m0 + 48, 1, Kf, Vf, KbC, VbC, PsC, qf, o,
                     m_lo, m_hi, l_lo, l_hi, tid, r, lc, rloc, rowq);
    else
        band_tile<4>(m0 + 48, 0, Kf, Vf, KbC, VbC, PsC, qf, o,
                     m_lo, m_hi, l_lo, l_hi, tid, r, lc, rloc, rowq);

    // epilogue: normalize, fp16, perm32 concatenated-head layout
    float inv_lo = 1.f / l_lo, inv_hi = 1.f / l_hi;
    __half* OPl = g_att + ((size_t)b * TT + rowq) * HID + h * HD;
    __half* OPh = g_att + ((size_t)b * TT + rowq + 8) * HID + h * HD;
    #pragma unroll
    for (int nf = 0; nf < 16; nf++) {
        int cb = (nf >> 2) * 32 + lc * 8 + ((nf >> 1) & 1) * 4 + (nf & 1) * 2;
        *(__half2*)&OPl[cb] = __floats2half2_rn(o[nf][0] * inv_lo, o[nf][1] * inv_lo);
        *(__half2*)&OPh[cb] = __floats2half2_rn(o[nf][2] * inv_hi, o[nf][3] * inv_hi);
    }
}

// ---------------------------------------------------------------------------
extern "C" void kernel_launch(void* const* d_in, const int* in_sizes, int n_in,
                              void* d_out, int out_size)
{
    const float* x  = (const float*)d_in[0];
    const float* Wq = (const float*)d_in[1];
    const float* Wk = (const float*)d_in[2];
    const float* Wv = (const float*)d_in[3];
    const float* Wo = (const float*)d_in[4];
    const int* isc  = (const int*)d_in[5];
    float* out = (float*)d_out;

    cudaFuncSetAttribute(proj_tc, cudaFuncAttributeMaxDynamicSharedMemorySize, GSMEM);
    cudaFuncSetAttribute(outproj_tc, cudaFuncAttributeMaxDynamicSharedMemorySize, GSMEM);
    cudaFuncSetAttribute(attn_tc, cudaFuncAttributeMaxDynamicSharedMemorySize, ATTN_SM);

    __half* d_xt;  cudaGetSymbolAddress((void**)&d_xt, g_xt);
    __half* d_wot; cudaGetSymbolAddress((void**)&d_wot, g_wot);

    prep_perm<<<(MTOT * HID / 32 + 255) / 256, 256>>>(x, d_xt, MTOT * HID / 32);
    prep_perm<<<(HID * HID / 32 + 255) / 256, 256>>>(Wo, d_wot, HID * HID / 32);
    prep_wt<<<dim3(HID / 32, HD / 32, 21), dim3(32, 8)>>>(Wq, Wk, Wv);

    proj_tc<<<dim3(MTOT / 128, 21), 128, GSMEM>>>();
    compact_k<<<dim3(CPAD / 64, NH * BB), 256>>>();
    compact_vT<<<dim3(CPAD / 32, HD / 32, NH * BB), dim3(32, 8)>>>();
    attn_tc<<<dim3(TT / 64, BB, NH), 128, ATTN_SM>>>(isc);
    outproj_tc<<<dim3(MTOT / 128, HID / 128), 128, GSMEM>>>(out);
}